// round 4
// baseline (speedup 1.0000x reference)
#include <cuda_runtime.h>

// CombPool2d: out = (w_avg^2)*avg_pool2x2(x) + (w_max^2)*max_pool2x2(x)
// x: (16,192,224,224) f32, w_avg/w_max: (1,192,1,1), out: (16,192,112,112)
//
// HBM-bound streaming kernel (~771 MB). R2 hit 89.7% DRAM cycles / 7.1 TB/s.
// R3: 8 output pixels per thread (8x LDG.128 front-batched, 2x STG.128),
// streaming cache hints (__ldcs/__stcs) since every byte is touched once.

#define IH 224
#define IW 224
#define OH 112
#define OW 112
#define C_CH 192
#define EW (OW / 8)          // 14 8-pixel chunks per output row

__global__ void __launch_bounds__(256)
combpool2d_kernel(const float* __restrict__ x,
                  const float* __restrict__ w_avg,
                  const float* __restrict__ w_max,
                  float* __restrict__ out,
                  int total_chunks)
{
    int i = blockIdx.x * blockDim.x + threadIdx.x;
    if (i >= total_chunks) return;

    // i -> (bc, oh, ew) with compile-time-constant divisors
    int ew = i % EW;
    int t  = i / EW;
    int oh = t % OH;
    int bc = t / OH;           // fused batch*channel, 0..3071
    int c  = bc % C_CH;

    float wa = __ldg(w_avg + c);
    float wm = __ldg(w_max + c);
    wa = wa * wa * 0.25f;      // fold 1/(K*K) into the avg coefficient
    wm = wm * wm;

    const float4* row0 = reinterpret_cast<const float4*>(
        x + (size_t)bc * (IH * IW) + (size_t)(2 * oh) * IW + ew * 16);
    const float4* row1 = row0 + (IW / 4);

    // 8 front-batched 128-bit streaming loads (MLP=8), no reuse -> evict-first
    float4 a0 = __ldcs(row0 + 0);
    float4 a1 = __ldcs(row0 + 1);
    float4 a2 = __ldcs(row0 + 2);
    float4 a3 = __ldcs(row0 + 3);
    float4 b0 = __ldcs(row1 + 0);
    float4 b1 = __ldcs(row1 + 1);
    float4 b2 = __ldcs(row1 + 2);
    float4 b3 = __ldcs(row1 + 3);

    float4 o0, o1;
    o0.x = wa * (a0.x + a0.y + b0.x + b0.y)
         + wm * fmaxf(fmaxf(a0.x, a0.y), fmaxf(b0.x, b0.y));
    o0.y = wa * (a0.z + a0.w + b0.z + b0.w)
         + wm * fmaxf(fmaxf(a0.z, a0.w), fmaxf(b0.z, b0.w));
    o0.z = wa * (a1.x + a1.y + b1.x + b1.y)
         + wm * fmaxf(fmaxf(a1.x, a1.y), fmaxf(b1.x, b1.y));
    o0.w = wa * (a1.z + a1.w + b1.z + b1.w)
         + wm * fmaxf(fmaxf(a1.z, a1.w), fmaxf(b1.z, b1.w));

    o1.x = wa * (a2.x + a2.y + b2.x + b2.y)
         + wm * fmaxf(fmaxf(a2.x, a2.y), fmaxf(b2.x, b2.y));
    o1.y = wa * (a2.z + a2.w + b2.z + b2.w)
         + wm * fmaxf(fmaxf(a2.z, a2.w), fmaxf(b2.z, b2.w));
    o1.z = wa * (a3.x + a3.y + b3.x + b3.y)
         + wm * fmaxf(fmaxf(a3.x, a3.y), fmaxf(b3.x, b3.y));
    o1.w = wa * (a3.z + a3.w + b3.z + b3.w)
         + wm * fmaxf(fmaxf(a3.z, a3.w), fmaxf(b3.z, b3.w));

    float4* dst = reinterpret_cast<float4*>(
        out + (size_t)bc * (OH * OW) + (size_t)oh * OW + ew * 8);
    __stcs(dst + 0, o0);
    __stcs(dst + 1, o1);
}

extern "C" void kernel_launch(void* const* d_in, const int* in_sizes, int n_in,
                              void* d_out, int out_size)
{
    const float* x     = (const float*)d_in[0];
    const float* w_avg = (const float*)d_in[1];
    const float* w_max = (const float*)d_in[2];
    float* out = (float*)d_out;

    int total_chunks = out_size / 8;              // 4,816,896
    int threads = 256;
    int blocks = (total_chunks + threads - 1) / threads;
    combpool2d_kernel<<<blocks, threads>>>(x, w_avg, w_max, out, total_chunks);
}

// round 5
// speedup vs baseline: 1.0787x; 1.0787x over previous
#include <cuda_runtime.h>

// CombPool2d: out = (w_avg^2)*avg_pool2x2(x) + (w_max^2)*max_pool2x2(x)
// x: (16,192,224,224) f32, w_avg/w_max: (1,192,1,1), out: (16,192,112,112)
//
// HBM-bound streaming kernel (~771 MB, floor ~96us @ 8TB/s).
// R4 layout: one thread per float4-column of the input row pair.
//   - 2x LDG.128 per thread, consecutive threads -> consecutive 16B:
//     100% sector utilization per load instruction (R2 had 50%/instr).
//   - horizontal 2:1 pooling happens entirely inside the float4,
//     vertical pooling across the two row loads -> one STG.64 per thread,
//     fully coalesced.

#define IH 224
#define IW 224
#define OH 112
#define OW 112
#define C_CH 192
#define FW (IW / 4)          // 56 float4 columns per input row

__global__ void __launch_bounds__(256)
combpool2d_kernel(const float* __restrict__ x,
                  const float* __restrict__ w_avg,
                  const float* __restrict__ w_max,
                  float* __restrict__ out,
                  int total)
{
    int i = blockIdx.x * blockDim.x + threadIdx.x;
    if (i >= total) return;

    // i -> (bc, oh, fw) with compile-time-constant divisors
    int fw = i % FW;
    int t  = i / FW;
    int oh = t % OH;
    int bc = t / OH;           // fused batch*channel, 0..3071
    int c  = bc % C_CH;

    float wa = __ldg(w_avg + c);
    float wm = __ldg(w_max + c);
    wa = wa * wa * 0.25f;      // fold 1/(K*K) into the avg coefficient
    wm = wm * wm;

    const float4* r0 = reinterpret_cast<const float4*>(
        x + (size_t)bc * (IH * IW) + (size_t)(2 * oh) * IW) + fw;
    const float4* r1 = r0 + (IW / 4);

    float4 a = *r0;            // row 2*oh,   cols [4fw, 4fw+4)
    float4 b = *r1;            // row 2*oh+1, cols [4fw, 4fw+4)

    float2 o;
    o.x = wa * (a.x + a.y + b.x + b.y)
        + wm * fmaxf(fmaxf(a.x, a.y), fmaxf(b.x, b.y));
    o.y = wa * (a.z + a.w + b.z + b.w)
        + wm * fmaxf(fmaxf(a.z, a.w), fmaxf(b.z, b.w));

    reinterpret_cast<float2*>(
        out + (size_t)bc * (OH * OW) + (size_t)oh * OW)[fw] = o;
}

extern "C" void kernel_launch(void* const* d_in, const int* in_sizes, int n_in,
                              void* d_out, int out_size)
{
    const float* x     = (const float*)d_in[0];
    const float* w_avg = (const float*)d_in[1];
    const float* w_max = (const float*)d_in[2];
    float* out = (float*)d_out;

    int total = out_size / 2;                     // 19,267,584 threads
    int threads = 256;
    int blocks = (total + threads - 1) / threads;
    combpool2d_kernel<<<blocks, threads>>>(x, w_avg, w_max, out, total);
}

// round 9
// speedup vs baseline: 1.0871x; 1.0078x over previous
#include <cuda_runtime.h>

// CombPool2d: out = (w_avg^2)*avg_pool2x2(x) + (w_max^2)*max_pool2x2(x)
// x: (16,192,224,224) f32, w_avg/w_max: (1,192,1,1), out: (16,192,112,112)
//
// HBM-bound streaming kernel (~771 MB, floor ~96us @ 8TB/s spec).
// R5: sm_100+ 256-bit vector loads (ld.global.v8.f32). Each thread:
//   2x LDG.256 (row0/row1, 32B each, warp-dense 1024B/instruction)
//   -> 4 output pixels -> 1x STG.128.
// Combines R2's 64B-per-thread with R4's 100%-dense per-instruction sectors,
// at half the load-instruction count of either.

#define IH 224
#define IW 224
#define OH 112
#define OW 112
#define C_CH 192
#define EW (IW / 8)          // 28 8-float chunks per input row

__global__ void __launch_bounds__(256)
combpool2d_kernel(const float* __restrict__ x,
                  const float* __restrict__ w_avg,
                  const float* __restrict__ w_max,
                  float* __restrict__ out,
                  int total)
{
    int i = blockIdx.x * blockDim.x + threadIdx.x;
    if (i >= total) return;

    // i -> (bc, oh, ew) with compile-time-constant divisors
    int ew = i % EW;
    int t  = i / EW;
    int oh = t % OH;
    int bc = t / OH;           // fused batch*channel, 0..3071
    int c  = bc % C_CH;

    float wa = __ldg(w_avg + c);
    float wm = __ldg(w_max + c);
    wa = wa * wa * 0.25f;      // fold 1/(K*K) into the avg coefficient
    wm = wm * wm;

    const float* r0 = x + (size_t)bc * (IH * IW) + (size_t)(2 * oh) * IW + ew * 8;
    const float* r1 = r0 + IW;

    // Two 256-bit loads: 8 floats from each input row (32B, 32B-aligned).
    float a0, a1, a2, a3, a4, a5, a6, a7;
    float b0, b1, b2, b3, b4, b5, b6, b7;
    asm volatile("ld.global.nc.v8.f32 {%0,%1,%2,%3,%4,%5,%6,%7}, [%8];"
                 : "=f"(a0), "=f"(a1), "=f"(a2), "=f"(a3),
                   "=f"(a4), "=f"(a5), "=f"(a6), "=f"(a7)
                 : "l"(r0));
    asm volatile("ld.global.nc.v8.f32 {%0,%1,%2,%3,%4,%5,%6,%7}, [%8];"
                 : "=f"(b0), "=f"(b1), "=f"(b2), "=f"(b3),
                   "=f"(b4), "=f"(b5), "=f"(b6), "=f"(b7)
                 : "l"(r1));

    float4 o;
    o.x = wa * (a0 + a1 + b0 + b1) + wm * fmaxf(fmaxf(a0, a1), fmaxf(b0, b1));
    o.y = wa * (a2 + a3 + b2 + b3) + wm * fmaxf(fmaxf(a2, a3), fmaxf(b2, b3));
    o.z = wa * (a4 + a5 + b4 + b5) + wm * fmaxf(fmaxf(a4, a5), fmaxf(b4, b5));
    o.w = wa * (a6 + a7 + b6 + b7) + wm * fmaxf(fmaxf(a6, a7), fmaxf(b6, b7));

    *reinterpret_cast<float4*>(
        out + (size_t)bc * (OH * OW) + (size_t)oh * OW + ew * 4) = o;
}

extern "C" void kernel_launch(void* const* d_in, const int* in_sizes, int n_in,
                              void* d_out, int out_size)
{
    const float* x     = (const float*)d_in[0];
    const float* w_avg = (const float*)d_in[1];
    const float* w_max = (const float*)d_in[2];
    float* out = (float*)d_out;

    int total = out_size / 4;                     // 9,633,792 threads
    int threads = 256;
    int blocks = (total + threads - 1) / threads;
    combpool2d_kernel<<<blocks, threads>>>(x, w_avg, w_max, out, total);
}